// round 8
// baseline (speedup 1.0000x reference)
#include <cuda_runtime.h>
#include <math.h>

#define N_NODES 50000
#define N_EDGES 600000
#define DIM 128

#define SCAN_BLK 256
#define SCAN_NBLKS ((N_NODES + SCAN_BLK - 1) / SCAN_BLK)   // 196

// ---------------- scratch (static device globals) ------------------------------
__device__ int  g_count[N_NODES];
__device__ int  g_offsets[N_NODES + 1];
__device__ int  g_blocksum[SCAN_NBLKS];
__device__ int  g_blockoff[SCAN_NBLKS];
__device__ int  g_plocal[N_EDGES];       // edge -> rank within its dst segment
__device__ int2 g_csr[N_EDGES];          // {src node, original edge id} per CSR slot

// ---------------- CSR build -----------------------------------------------------
// count + assign within-segment rank in one atomic
__global__ void count_kernel(const int* __restrict__ dst) {
    int e = blockIdx.x * blockDim.x + threadIdx.x;
    if (e < N_EDGES) g_plocal[e] = atomicAdd(&g_count[dst[e]], 1);
}

// Level-1: per-block exclusive scan of 256 counts; write local prefix + block sum
__global__ void __launch_bounds__(SCAN_BLK) scanA_kernel() {
    __shared__ int s[SCAN_BLK];
    const int tid = threadIdx.x;
    const int i   = blockIdx.x * SCAN_BLK + tid;
    int v = (i < N_NODES) ? g_count[i] : 0;
    s[tid] = v;
    __syncthreads();
    for (int off = 1; off < SCAN_BLK; off <<= 1) {
        int t = (tid >= off) ? s[tid - off] : 0;
        __syncthreads();
        s[tid] += t;
        __syncthreads();
    }
    if (i < N_NODES) g_offsets[i] = s[tid] - v;          // local exclusive prefix
    if (tid == SCAN_BLK - 1) g_blocksum[blockIdx.x] = s[tid];
}

// Level-2: single block scans the block sums (exclusive)
__global__ void __launch_bounds__(SCAN_BLK) scanB_kernel() {
    __shared__ int s[SCAN_BLK];
    const int tid = threadIdx.x;
    int v = (tid < SCAN_NBLKS) ? g_blocksum[tid] : 0;
    s[tid] = v;
    __syncthreads();
    for (int off = 1; off < SCAN_BLK; off <<= 1) {
        int t = (tid >= off) ? s[tid - off] : 0;
        __syncthreads();
        s[tid] += t;
        __syncthreads();
    }
    if (tid < SCAN_NBLKS) g_blockoff[tid] = s[tid] - v;
    if (tid == SCAN_BLK - 1) g_offsets[N_NODES] = s[tid];   // total = N_EDGES
}

// Level-3: add block offsets
__global__ void __launch_bounds__(SCAN_BLK) scanC_kernel() {
    const int i = blockIdx.x * SCAN_BLK + threadIdx.x;
    if (i < N_NODES)
        g_offsets[i] += g_blockoff[blockIdx.x];
}

// atomic-free scatter: slot = offsets[dst] + precomputed local rank
__global__ void scatter_kernel(const int* __restrict__ src,
                               const int* __restrict__ dst) {
    int e = blockIdx.x * blockDim.x + threadIdx.x;
    if (e < N_EDGES) {
        const int p = g_offsets[dst[e]] + g_plocal[e];
        g_csr[p] = make_int2(src[e], e);
    }
}

// ---------------- fused per-node kernel: logits + softmax + aggregate -----------
// HALF-WARP per edge: 16 lanes cover 128 dims (8 floats each); the two halves of
// a warp process edges i and i+1 of the same node concurrently -> 2x MLP, and the
// dot reduction is 4 shfl levels instead of 5. Halves are merged once at the end.
// No running-max (logits are sigmoid-gated unit-scale dots; exp overflow impossible).
__global__ void __launch_bounds__(256) fused_node_kernel(
        const float* __restrict__ h_v,
        const float* __restrict__ h_d,
        const float* __restrict__ W_pi,
        const float* __restrict__ W_M,
        float*       __restrict__ out) {
    const int lane = threadIdx.x & 31;
    const int half = lane >> 4;          // 0 or 1: which edge of the pair
    const int hl   = lane & 15;          // lane within half: dims [8*hl, 8*hl+8)
    const int n    = (blockIdx.x * blockDim.x + threadIdx.x) >> 5;
    if (n >= N_NODES) return;

    const int start = g_offsets[n];
    const int end   = g_offsets[n + 1];

    float4 acc0 = make_float4(0.f, 0.f, 0.f, 0.f);
    float4 acc1 = make_float4(0.f, 0.f, 0.f, 0.f);
    float  ssum = 0.f;

    if (end > start) {
        const unsigned hm = half ? 0xFFFF0000u : 0x0000FFFFu;

        const float4* Wp  = (const float4*)W_pi;
        const float4* Wa  = (const float4*)W_M;          // prod part
        const float4* Wb  = (const float4*)(W_M + DIM);  // h_d part
        const float4 wp0 = Wp[2*hl], wp1 = Wp[2*hl + 1];
        const float4 wa0 = Wa[2*hl], wa1 = Wa[2*hl + 1];
        const float4 wb0 = Wb[2*hl], wb1 = Wb[2*hl + 1];
        const float4* fdp = (const float4*)(h_v + (size_t)n * DIM);
        const float4 fd0 = fdp[2*hl], fd1 = fdp[2*hl + 1];

        int  i     = start + half;
        bool valid = (i < end);

        // ---- prefetch edge for this half ----
        int2 se; float4 fsA, fsB, hdA, hdB;
        if (valid) {
            se = __ldg(&g_csr[i]);
            const float4* fp = (const float4*)(h_v + (size_t)se.x * DIM);
            fsA = fp[2*hl]; fsB = fp[2*hl + 1];
            const float4* hp = (const float4*)(h_d + (size_t)se.y * DIM);
            hdA = __ldcs(hp + 2*hl); hdB = __ldcs(hp + 2*hl + 1);
        }

        while (valid) {
            const int  inext = i + 2;
            const bool vnext = (inext < end);
            int2 se2; float4 fsA2, fsB2, hdA2, hdB2;
            if (vnext) {
                se2 = __ldg(&g_csr[inext]);
                const float4* fp = (const float4*)(h_v + (size_t)se2.x * DIM);
                fsA2 = fp[2*hl]; fsB2 = fp[2*hl + 1];
                const float4* hp = (const float4*)(h_d + (size_t)se2.y * DIM);
                hdA2 = __ldcs(hp + 2*hl); hdB2 = __ldcs(hp + 2*hl + 1);
            }

            // products over this lane's 8 dims
            const float pA0 = fsA.x * fd0.x, pA1 = fsA.y * fd0.y;
            const float pA2 = fsA.z * fd0.z, pA3 = fsA.w * fd0.w;
            const float pB0 = fsB.x * fd1.x, pB1 = fsB.y * fd1.y;
            const float pB2 = fsB.z * fd1.z, pB3 = fsB.w * fd1.w;

            float dot1 = pA0 * hdA.x * wp0.x + pA1 * hdA.y * wp0.y
                       + pA2 * hdA.z * wp0.z + pA3 * hdA.w * wp0.w
                       + pB0 * hdB.x * wp1.x + pB1 * hdB.y * wp1.y
                       + pB2 * hdB.z * wp1.z + pB3 * hdB.w * wp1.w;
            float dot2 = pA0 * wa0.x + pA1 * wa0.y + pA2 * wa0.z + pA3 * wa0.w
                       + pB0 * wa1.x + pB1 * wa1.y + pB2 * wa1.z + pB3 * wa1.w
                       + hdA.x * wb0.x + hdA.y * wb0.y + hdA.z * wb0.z + hdA.w * wb0.w
                       + hdB.x * wb1.x + hdB.y * wb1.y + hdB.z * wb1.z + hdB.w * wb1.w;

            // 4-level reduction within the 16-lane half
            #pragma unroll
            for (int off = 8; off > 0; off >>= 1) {
                dot1 += __shfl_xor_sync(hm, dot1, off);
                dot2 += __shfl_xor_sync(hm, dot2, off);
            }

            const float mask = __fdividef(1.0f, 1.0f + __expf(-dot2));
            const float p    = __expf(dot1 * mask);    // uniform across the half

            ssum  += p;
            acc0.x += p * fsA.x; acc0.y += p * fsA.y;
            acc0.z += p * fsA.z; acc0.w += p * fsA.w;
            acc1.x += p * fsB.x; acc1.y += p * fsB.y;
            acc1.z += p * fsB.z; acc1.w += p * fsB.w;

            i = inext; valid = vnext;
            if (valid) { se = se2; fsA = fsA2; fsB = fsB2; hdA = hdA2; hdB = hdB2; }
        }

        __syncwarp();   // reconverge halves (they may differ by one iteration)
        // merge the two halves: lane l <-> lane l^16 hold the same dims
        ssum  += __shfl_xor_sync(0xFFFFFFFFu, ssum,  16);
        acc0.x += __shfl_xor_sync(0xFFFFFFFFu, acc0.x, 16);
        acc0.y += __shfl_xor_sync(0xFFFFFFFFu, acc0.y, 16);
        acc0.z += __shfl_xor_sync(0xFFFFFFFFu, acc0.z, 16);
        acc0.w += __shfl_xor_sync(0xFFFFFFFFu, acc0.w, 16);
        acc1.x += __shfl_xor_sync(0xFFFFFFFFu, acc1.x, 16);
        acc1.y += __shfl_xor_sync(0xFFFFFFFFu, acc1.y, 16);
        acc1.z += __shfl_xor_sync(0xFFFFFFFFu, acc1.z, 16);
        acc1.w += __shfl_xor_sync(0xFFFFFFFFu, acc1.w, 16);

        const float inv = 1.0f / ssum;
        acc0.x *= inv; acc0.y *= inv; acc0.z *= inv; acc0.w *= inv;
        acc1.x *= inv; acc1.y *= inv; acc1.z *= inv; acc1.w *= inv;
    }

    if (half == 0) {   // lanes 0-15 write the full 512B row
        float4* o = (float4*)(out + (size_t)n * DIM);
        o[2*hl]     = acc0;
        o[2*hl + 1] = acc1;
    }
}

// ---------------- launch --------------------------------------------------------
extern "C" void kernel_launch(void* const* d_in, const int* in_sizes, int n_in,
                              void* d_out, int out_size) {
    const float* h_v  = (const float*)d_in[0];
    const float* h_d  = (const float*)d_in[1];
    const float* W_pi = (const float*)d_in[2];
    const float* W_M  = (const float*)d_in[3];
    const int*   src  = (const int*)d_in[4];
    const int*   dst  = (const int*)d_in[5];
    float*       out  = (float*)d_out;

    void* count_addr = nullptr;
    cudaGetSymbolAddress(&count_addr, g_count);
    cudaMemsetAsync(count_addr, 0, N_NODES * sizeof(int));

    count_kernel<<<(N_EDGES + 255) / 256, 256>>>(dst);
    scanA_kernel<<<SCAN_NBLKS, SCAN_BLK>>>();
    scanB_kernel<<<1, SCAN_BLK>>>();
    scanC_kernel<<<SCAN_NBLKS, SCAN_BLK>>>();
    scatter_kernel<<<(N_EDGES + 255) / 256, 256>>>(src, dst);

    fused_node_kernel<<<(N_NODES * 32 + 255) / 256, 256>>>(h_v, h_d, W_pi, W_M, out);
}

// round 9
// speedup vs baseline: 1.4187x; 1.4187x over previous
#include <cuda_runtime.h>
#include <math.h>

#define N_NODES 50000
#define N_EDGES 600000
#define DIM 128

#define SCAN_BLK 256
#define SCAN_NBLKS ((N_NODES + SCAN_BLK - 1) / SCAN_BLK)   // 196

// ---------------- scratch (static device globals) ------------------------------
__device__ int  g_count[N_NODES];
__device__ int  g_offsets[N_NODES + 1];
__device__ int  g_blocksum[SCAN_NBLKS];
__device__ int  g_blockoff[SCAN_NBLKS];
__device__ int  g_plocal[N_EDGES];       // edge -> rank within its dst segment
__device__ int2 g_csr[N_EDGES];          // {src node, original edge id} per CSR slot

// ---------------- CSR build -----------------------------------------------------
// count + assign within-segment rank in one atomic
__global__ void count_kernel(const int* __restrict__ dst) {
    int e = blockIdx.x * blockDim.x + threadIdx.x;
    if (e < N_EDGES) g_plocal[e] = atomicAdd(&g_count[dst[e]], 1);
}

// Level-1: per-block exclusive scan of 256 counts; write local prefix + block sum
__global__ void __launch_bounds__(SCAN_BLK) scanA_kernel() {
    __shared__ int s[SCAN_BLK];
    const int tid = threadIdx.x;
    const int i   = blockIdx.x * SCAN_BLK + tid;
    int v = (i < N_NODES) ? g_count[i] : 0;
    s[tid] = v;
    __syncthreads();
    for (int off = 1; off < SCAN_BLK; off <<= 1) {
        int t = (tid >= off) ? s[tid - off] : 0;
        __syncthreads();
        s[tid] += t;
        __syncthreads();
    }
    if (i < N_NODES) g_offsets[i] = s[tid] - v;          // local exclusive prefix
    if (tid == SCAN_BLK - 1) g_blocksum[blockIdx.x] = s[tid];
}

// Level-2: single block scans the block sums (exclusive)
__global__ void __launch_bounds__(SCAN_BLK) scanB_kernel() {
    __shared__ int s[SCAN_BLK];
    const int tid = threadIdx.x;
    int v = (tid < SCAN_NBLKS) ? g_blocksum[tid] : 0;
    s[tid] = v;
    __syncthreads();
    for (int off = 1; off < SCAN_BLK; off <<= 1) {
        int t = (tid >= off) ? s[tid - off] : 0;
        __syncthreads();
        s[tid] += t;
        __syncthreads();
    }
    if (tid < SCAN_NBLKS) g_blockoff[tid] = s[tid] - v;
    if (tid == SCAN_BLK - 1) g_offsets[N_NODES] = s[tid];   // total = N_EDGES
}

// Level-3: add block offsets
__global__ void __launch_bounds__(SCAN_BLK) scanC_kernel() {
    const int i = blockIdx.x * SCAN_BLK + threadIdx.x;
    if (i < N_NODES)
        g_offsets[i] += g_blockoff[blockIdx.x];
}

// atomic-free scatter: slot = offsets[dst] + precomputed local rank
__global__ void scatter_kernel(const int* __restrict__ src,
                               const int* __restrict__ dst) {
    int e = blockIdx.x * blockDim.x + threadIdx.x;
    if (e < N_EDGES) {
        const int p = g_offsets[dst[e]] + g_plocal[e];
        g_csr[p] = make_int2(src[e], e);
    }
}

// ---------------- fused per-node kernel: logits + softmax + aggregate -----------
// One warp per node, TWO edges per iteration (uniform control flow, no divergence).
// All 4 row-gathers (fs_a, hd_a, fs_b, hd_b) issue before any reduction -> MLP 4,
// and the two edges' shfl trees interleave (4 independent chains). Odd tail edge:
// edge B duplicates edge A's loads and its contribution is masked to zero.
// No running-max (logits are sigmoid-gated unit-scale dots; exp overflow impossible).
__global__ void __launch_bounds__(256) fused_node_kernel(
        const float* __restrict__ h_v,
        const float* __restrict__ h_d,
        const float* __restrict__ W_pi,
        const float* __restrict__ W_M,
        float*       __restrict__ out) {
    const int lane = threadIdx.x & 31;
    const int n    = (blockIdx.x * blockDim.x + threadIdx.x) >> 5;
    if (n >= N_NODES) return;

    const int start = g_offsets[n];
    const int end   = g_offsets[n + 1];

    float4 acc  = make_float4(0.f, 0.f, 0.f, 0.f);
    float  ssum = 0.f;          // running sum of exp(logit) (uniform across lanes)

    if (end > start) {
        // per-lane weights + this node's dst feature row (read once)
        const float4 wp  = ((const float4*)W_pi)[lane];
        const float4 wm1 = ((const float4*)W_M)[lane];          // prod part
        const float4 wm2 = ((const float4*)(W_M + DIM))[lane];  // h_d part
        const float4 fd  = ((const float4*)(h_v + (size_t)n * DIM))[lane];

        for (int i = start; i < end; i += 2) {
            const bool hasB = (i + 1 < end);

            // ---- issue all 4 row-gathers up front (uniform: tail duplicates A) --
            const int2 sa = __ldg(&g_csr[i]);
            const int2 sb = hasB ? __ldg(&g_csr[i + 1]) : sa;

            const float4 fa = ((const float4*)(h_v + (size_t)sa.x * DIM))[lane];
            const float4 ha = __ldcs((const float4*)(h_d + (size_t)sa.y * DIM) + lane);
            const float4 fb = ((const float4*)(h_v + (size_t)sb.x * DIM))[lane];
            const float4 hb = __ldcs((const float4*)(h_d + (size_t)sb.y * DIM) + lane);

            // ---- edge A partials ----
            const float pa0 = fa.x * fd.x, pa1 = fa.y * fd.y;
            const float pa2 = fa.z * fd.z, pa3 = fa.w * fd.w;
            float d1a = pa0 * ha.x * wp.x + pa1 * ha.y * wp.y
                      + pa2 * ha.z * wp.z + pa3 * ha.w * wp.w;
            float d2a = pa0 * wm1.x + pa1 * wm1.y + pa2 * wm1.z + pa3 * wm1.w
                      + ha.x * wm2.x + ha.y * wm2.y + ha.z * wm2.z + ha.w * wm2.w;

            // ---- edge B partials ----
            const float pb0 = fb.x * fd.x, pb1 = fb.y * fd.y;
            const float pb2 = fb.z * fd.z, pb3 = fb.w * fd.w;
            float d1b = pb0 * hb.x * wp.x + pb1 * hb.y * wp.y
                      + pb2 * hb.z * wp.z + pb3 * hb.w * wp.w;
            float d2b = pb0 * wm1.x + pb1 * wm1.y + pb2 * wm1.z + pb3 * wm1.w
                      + hb.x * wm2.x + hb.y * wm2.y + hb.z * wm2.z + hb.w * wm2.w;

            // ---- interleaved 5-level reductions (4 independent chains) ----
            #pragma unroll
            for (int off = 16; off > 0; off >>= 1) {
                d1a += __shfl_xor_sync(0xFFFFFFFFu, d1a, off);
                d2a += __shfl_xor_sync(0xFFFFFFFFu, d2a, off);
                d1b += __shfl_xor_sync(0xFFFFFFFFu, d1b, off);
                d2b += __shfl_xor_sync(0xFFFFFFFFu, d2b, off);
            }

            const float maskA = __fdividef(1.0f, 1.0f + __expf(-d2a));
            const float maskB = __fdividef(1.0f, 1.0f + __expf(-d2b));
            const float pA    = __expf(d1a * maskA);
            const float pB    = hasB ? __expf(d1b * maskB) : 0.0f;   // mask tail

            ssum  += pA + pB;
            acc.x += pA * fa.x + pB * fb.x;
            acc.y += pA * fa.y + pB * fb.y;
            acc.z += pA * fa.z + pB * fb.z;
            acc.w += pA * fa.w + pB * fb.w;
        }
        const float inv = 1.0f / ssum;
        acc.x *= inv; acc.y *= inv; acc.z *= inv; acc.w *= inv;
    }
    ((float4*)(out + (size_t)n * DIM))[lane] = acc;   // single coalesced store
}

// ---------------- launch --------------------------------------------------------
extern "C" void kernel_launch(void* const* d_in, const int* in_sizes, int n_in,
                              void* d_out, int out_size) {
    const float* h_v  = (const float*)d_in[0];
    const float* h_d  = (const float*)d_in[1];
    const float* W_pi = (const float*)d_in[2];
    const float* W_M  = (const float*)d_in[3];
    const int*   src  = (const int*)d_in[4];
    const int*   dst  = (const int*)d_in[5];
    float*       out  = (float*)d_out;

    void* count_addr = nullptr;
    cudaGetSymbolAddress(&count_addr, g_count);
    cudaMemsetAsync(count_addr, 0, N_NODES * sizeof(int));

    count_kernel<<<(N_EDGES + 255) / 256, 256>>>(dst);
    scanA_kernel<<<SCAN_NBLKS, SCAN_BLK>>>();
    scanB_kernel<<<1, SCAN_BLK>>>();
    scanC_kernel<<<SCAN_NBLKS, SCAN_BLK>>>();
    scatter_kernel<<<(N_EDGES + 255) / 256, 256>>>(src, dst);

    fused_node_kernel<<<(N_NODES * 32 + 255) / 256, 256>>>(h_v, h_d, W_pi, W_M, out);
}

// round 10
// speedup vs baseline: 1.4472x; 1.0201x over previous
#include <cuda_runtime.h>
#include <math.h>

#define N_NODES 50000
#define N_EDGES 600000
#define DIM 128

#define SCAN_BLK 256
#define SCAN_NBLKS ((N_NODES + SCAN_BLK - 1) / SCAN_BLK)   // 196

// ---------------- scratch (static device globals) ------------------------------
__device__ int  g_count[N_NODES];
__device__ int  g_offsets[N_NODES + 1];   // LOCAL exclusive prefix within scan-block
__device__ int  g_blocksum[SCAN_NBLKS];
__device__ int  g_blockoff[SCAN_NBLKS];   // scan-block base offset
__device__ int  g_plocal[N_EDGES];        // edge -> rank within its dst segment
__device__ int2 g_csr[N_EDGES];           // {src node, original edge id} per CSR slot

// ---------------- CSR build -----------------------------------------------------
// count + assign within-segment rank in one atomic
__global__ void count_kernel(const int* __restrict__ dst) {
    int e = blockIdx.x * blockDim.x + threadIdx.x;
    if (e < N_EDGES) g_plocal[e] = atomicAdd(&g_count[dst[e]], 1);
}

// Level-1: per-block exclusive scan of 256 counts; write local prefix + block sum
__global__ void __launch_bounds__(SCAN_BLK) scanA_kernel() {
    __shared__ int s[SCAN_BLK];
    const int tid = threadIdx.x;
    const int i   = blockIdx.x * SCAN_BLK + tid;
    int v = (i < N_NODES) ? g_count[i] : 0;
    s[tid] = v;
    __syncthreads();
    for (int off = 1; off < SCAN_BLK; off <<= 1) {
        int t = (tid >= off) ? s[tid - off] : 0;
        __syncthreads();
        s[tid] += t;
        __syncthreads();
    }
    if (i < N_NODES) g_offsets[i] = s[tid] - v;          // local exclusive prefix
    if (tid == SCAN_BLK - 1) g_blocksum[blockIdx.x] = s[tid];
}

// Level-2: single block scans the block sums (exclusive) -> g_blockoff
__global__ void __launch_bounds__(SCAN_BLK) scanB_kernel() {
    __shared__ int s[SCAN_BLK];
    const int tid = threadIdx.x;
    int v = (tid < SCAN_NBLKS) ? g_blocksum[tid] : 0;
    s[tid] = v;
    __syncthreads();
    for (int off = 1; off < SCAN_BLK; off <<= 1) {
        int t = (tid >= off) ? s[tid - off] : 0;
        __syncthreads();
        s[tid] += t;
        __syncthreads();
    }
    if (tid < SCAN_NBLKS) g_blockoff[tid] = s[tid] - v;
}

// atomic-free scatter; global slot = local prefix + scan-block base + local rank
__global__ void scatter_kernel(const int* __restrict__ src,
                               const int* __restrict__ dst) {
    int e = blockIdx.x * blockDim.x + threadIdx.x;
    if (e < N_EDGES) {
        const int d = dst[e];
        const int p = g_offsets[d] + g_blockoff[d >> 8] + g_plocal[e];
        g_csr[p] = make_int2(src[e], e);
    }
}

// ---------------- fused per-node kernel: logits + softmax + aggregate -----------
// One warp per node, FOUR edges per iteration (uniform control flow). All 8 row
// gathers issue before any reduction -> 8 loads in flight per warp; the 8 shfl
// reduction chains interleave. Tail edges duplicate edge A's loads (L1 hits) and
// are masked out of the accumulation. No running-max (sigmoid-gated unit-scale
// logits cannot overflow fp32 exp).
__global__ void __launch_bounds__(256) fused_node_kernel(
        const float* __restrict__ h_v,
        const float* __restrict__ h_d,
        const float* __restrict__ W_pi,
        const float* __restrict__ W_M,
        float*       __restrict__ out) {
    const int lane = threadIdx.x & 31;
    const int n    = (blockIdx.x * blockDim.x + threadIdx.x) >> 5;
    if (n >= N_NODES) return;

    const int start = g_offsets[n] + g_blockoff[n >> 8];
    const int end   = (n + 1 == N_NODES)
                    ? N_EDGES
                    : g_offsets[n + 1] + g_blockoff[(n + 1) >> 8];

    float4 acc  = make_float4(0.f, 0.f, 0.f, 0.f);
    float  ssum = 0.f;          // running sum of exp(logit) (uniform across lanes)

    if (end > start) {
        // per-lane weights + this node's dst feature row (read once)
        const float4 wp  = ((const float4*)W_pi)[lane];
        const float4 wm1 = ((const float4*)W_M)[lane];          // prod part
        const float4 wm2 = ((const float4*)(W_M + DIM))[lane];  // h_d part
        const float4 fdv = ((const float4*)(h_v + (size_t)n * DIM))[lane];

        for (int i = start; i < end; i += 4) {
            const int last = end - 1;
            const int iB = min(i + 1, last);
            const int iC = min(i + 2, last);
            const int iD = min(i + 3, last);
            const bool hasB = (i + 1 < end);
            const bool hasC = (i + 2 < end);
            const bool hasD = (i + 3 < end);

            // ---- issue all 8 row-gathers up front ----
            const int2 sa = __ldg(&g_csr[i]);
            const int2 sb = __ldg(&g_csr[iB]);
            const int2 sc = __ldg(&g_csr[iC]);
            const int2 sd = __ldg(&g_csr[iD]);

            const float4 fa = ((const float4*)(h_v + (size_t)sa.x * DIM))[lane];
            const float4 fb = ((const float4*)(h_v + (size_t)sb.x * DIM))[lane];
            const float4 fc = ((const float4*)(h_v + (size_t)sc.x * DIM))[lane];
            const float4 fe = ((const float4*)(h_v + (size_t)sd.x * DIM))[lane];
            const float4 ha = __ldcs((const float4*)(h_d + (size_t)sa.y * DIM) + lane);
            const float4 hb = __ldcs((const float4*)(h_d + (size_t)sb.y * DIM) + lane);
            const float4 hc = __ldcs((const float4*)(h_d + (size_t)sc.y * DIM) + lane);
            const float4 he = __ldcs((const float4*)(h_d + (size_t)sd.y * DIM) + lane);

            // ---- per-edge partial dots over this lane's 4 dims ----
            const float pa0 = fa.x * fdv.x, pa1 = fa.y * fdv.y;
            const float pa2 = fa.z * fdv.z, pa3 = fa.w * fdv.w;
            float d1a = pa0 * ha.x * wp.x + pa1 * ha.y * wp.y
                      + pa2 * ha.z * wp.z + pa3 * ha.w * wp.w;
            float d2a = pa0 * wm1.x + pa1 * wm1.y + pa2 * wm1.z + pa3 * wm1.w
                      + ha.x * wm2.x + ha.y * wm2.y + ha.z * wm2.z + ha.w * wm2.w;

            const float pb0 = fb.x * fdv.x, pb1 = fb.y * fdv.y;
            const float pb2 = fb.z * fdv.z, pb3 = fb.w * fdv.w;
            float d1b = pb0 * hb.x * wp.x + pb1 * hb.y * wp.y
                      + pb2 * hb.z * wp.z + pb3 * hb.w * wp.w;
            float d2b = pb0 * wm1.x + pb1 * wm1.y + pb2 * wm1.z + pb3 * wm1.w
                      + hb.x * wm2.x + hb.y * wm2.y + hb.z * wm2.z + hb.w * wm2.w;

            const float pc0 = fc.x * fdv.x, pc1 = fc.y * fdv.y;
            const float pc2 = fc.z * fdv.z, pc3 = fc.w * fdv.w;
            float d1c = pc0 * hc.x * wp.x + pc1 * hc.y * wp.y
                      + pc2 * hc.z * wp.z + pc3 * hc.w * wp.w;
            float d2c = pc0 * wm1.x + pc1 * wm1.y + pc2 * wm1.z + pc3 * wm1.w
                      + hc.x * wm2.x + hc.y * wm2.y + hc.z * wm2.z + hc.w * wm2.w;

            const float pe0 = fe.x * fdv.x, pe1 = fe.y * fdv.y;
            const float pe2 = fe.z * fdv.z, pe3 = fe.w * fdv.w;
            float d1e = pe0 * he.x * wp.x + pe1 * he.y * wp.y
                      + pe2 * he.z * wp.z + pe3 * he.w * wp.w;
            float d2e = pe0 * wm1.x + pe1 * wm1.y + pe2 * wm1.z + pe3 * wm1.w
                      + he.x * wm2.x + he.y * wm2.y + he.z * wm2.z + he.w * wm2.w;

            // ---- 8 interleaved 5-level reductions ----
            #pragma unroll
            for (int off = 16; off > 0; off >>= 1) {
                d1a += __shfl_xor_sync(0xFFFFFFFFu, d1a, off);
                d2a += __shfl_xor_sync(0xFFFFFFFFu, d2a, off);
                d1b += __shfl_xor_sync(0xFFFFFFFFu, d1b, off);
                d2b += __shfl_xor_sync(0xFFFFFFFFu, d2b, off);
                d1c += __shfl_xor_sync(0xFFFFFFFFu, d1c, off);
                d2c += __shfl_xor_sync(0xFFFFFFFFu, d2c, off);
                d1e += __shfl_xor_sync(0xFFFFFFFFu, d1e, off);
                d2e += __shfl_xor_sync(0xFFFFFFFFu, d2e, off);
            }

            const float pA = __expf(d1a * __fdividef(1.0f, 1.0f + __expf(-d2a)));
            float pB = __expf(d1b * __fdividef(1.0f, 1.0f + __expf(-d2b)));
            float pC = __expf(d1c * __fdividef(1.0f, 1.0f + __expf(-d2c)));
            float pD = __expf(d1e * __fdividef(1.0f, 1.0f + __expf(-d2e)));
            pB = hasB ? pB : 0.0f;
            pC = hasC ? pC : 0.0f;
            pD = hasD ? pD : 0.0f;

            ssum  += (pA + pB) + (pC + pD);
            acc.x += pA * fa.x + pB * fb.x + pC * fc.x + pD * fe.x;
            acc.y += pA * fa.y + pB * fb.y + pC * fc.y + pD * fe.y;
            acc.z += pA * fa.z + pB * fb.z + pC * fc.z + pD * fe.z;
            acc.w += pA * fa.w + pB * fb.w + pC * fc.w + pD * fe.w;
        }
        const float inv = 1.0f / ssum;
        acc.x *= inv; acc.y *= inv; acc.z *= inv; acc.w *= inv;
    }
    ((float4*)(out + (size_t)n * DIM))[lane] = acc;   // single coalesced store
}

// ---------------- launch --------------------------------------------------------
extern "C" void kernel_launch(void* const* d_in, const int* in_sizes, int n_in,
                              void* d_out, int out_size) {
    const float* h_v  = (const float*)d_in[0];
    const float* h_d  = (const float*)d_in[1];
    const float* W_pi = (const float*)d_in[2];
    const float* W_M  = (const float*)d_in[3];
    const int*   src  = (const int*)d_in[4];
    const int*   dst  = (const int*)d_in[5];
    float*       out  = (float*)d_out;

    void* count_addr = nullptr;
    cudaGetSymbolAddress(&count_addr, g_count);
    cudaMemsetAsync(count_addr, 0, N_NODES * sizeof(int));

    count_kernel<<<(N_EDGES + 255) / 256, 256>>>(dst);
    scanA_kernel<<<SCAN_NBLKS, SCAN_BLK>>>();
    scanB_kernel<<<1, SCAN_BLK>>>();
    scatter_kernel<<<(N_EDGES + 255) / 256, 256>>>(src, dst);

    fused_node_kernel<<<(N_NODES * 32 + 255) / 256, 256>>>(h_v, h_d, W_pi, W_M, out);
}

// round 13
// speedup vs baseline: 1.5466x; 1.0687x over previous
#include <cuda_runtime.h>
#include <math.h>

#define N_NODES 50000
#define N_EDGES 600000
#define DIM 128

#define SCAN_BLK 256
#define SCAN_NBLKS ((N_NODES + SCAN_BLK - 1) / SCAN_BLK)   // 196

// ---------------- scratch (static device globals) ------------------------------
__device__ int  g_count[N_NODES];
__device__ int  g_offsets[N_NODES + 1];   // LOCAL exclusive prefix within scan-block
__device__ int  g_blocksum[SCAN_NBLKS];
__device__ int  g_blockoff[SCAN_NBLKS];   // scan-block base offset
__device__ int  g_plocal[N_EDGES];        // edge -> rank within its dst segment
__device__ int2 g_csr[N_EDGES];           // {src node, original edge id} per CSR slot

// ---------------- CSR build -----------------------------------------------------
// count + assign within-segment rank in one atomic
__global__ void count_kernel(const int* __restrict__ dst) {
    int e = blockIdx.x * blockDim.x + threadIdx.x;
    if (e < N_EDGES) g_plocal[e] = atomicAdd(&g_count[dst[e]], 1);
}

// Level-1: per-block exclusive scan of 256 counts; write local prefix + block sum
__global__ void __launch_bounds__(SCAN_BLK) scanA_kernel() {
    __shared__ int s[SCAN_BLK];
    const int tid = threadIdx.x;
    const int i   = blockIdx.x * SCAN_BLK + tid;
    int v = (i < N_NODES) ? g_count[i] : 0;
    s[tid] = v;
    __syncthreads();
    for (int off = 1; off < SCAN_BLK; off <<= 1) {
        int t = (tid >= off) ? s[tid - off] : 0;
        __syncthreads();
        s[tid] += t;
        __syncthreads();
    }
    if (i < N_NODES) g_offsets[i] = s[tid] - v;          // local exclusive prefix
    if (tid == SCAN_BLK - 1) g_blocksum[blockIdx.x] = s[tid];
}

// Level-2: single block scans the block sums (exclusive) -> g_blockoff
__global__ void __launch_bounds__(SCAN_BLK) scanB_kernel() {
    __shared__ int s[SCAN_BLK];
    const int tid = threadIdx.x;
    int v = (tid < SCAN_NBLKS) ? g_blocksum[tid] : 0;
    s[tid] = v;
    __syncthreads();
    for (int off = 1; off < SCAN_BLK; off <<= 1) {
        int t = (tid >= off) ? s[tid - off] : 0;
        __syncthreads();
        s[tid] += t;
        __syncthreads();
    }
    if (tid < SCAN_NBLKS) g_blockoff[tid] = s[tid] - v;
}

// atomic-free scatter; global slot = local prefix + scan-block base + local rank
__global__ void scatter_kernel(const int* __restrict__ src,
                               const int* __restrict__ dst) {
    int e = blockIdx.x * blockDim.x + threadIdx.x;
    if (e < N_EDGES) {
        const int d = dst[e];
        const int p = g_offsets[d] + g_blockoff[d >> 8] + g_plocal[e];
        g_csr[p] = make_int2(src[e], e);
    }
}

// ---------------- fused per-node kernel: logits + softmax + aggregate -----------
// One warp per node, FOUR edges per iteration (uniform control flow). All 8 row
// gathers issue before any reduction -> 8 loads in flight per warp; the 8 shfl
// reduction chains interleave. Tail edges duplicate the last edge's loads (L1
// hits) and are masked out. No running-max (sigmoid-gated unit-scale logits
// cannot overflow fp32 exp). Block=128: 4 nodes per CTA reduces the straggler
// tail (max-of-4 degrees instead of max-of-8).
__global__ void __launch_bounds__(128) fused_node_kernel(
        const float* __restrict__ h_v,
        const float* __restrict__ h_d,
        const float* __restrict__ W_pi,
        const float* __restrict__ W_M,
        float*       __restrict__ out) {
    const int lane = threadIdx.x & 31;
    const int n    = (blockIdx.x * blockDim.x + threadIdx.x) >> 5;
    if (n >= N_NODES) return;

    const int start = g_offsets[n] + g_blockoff[n >> 8];
    const int end   = (n + 1 == N_NODES)
                    ? N_EDGES
                    : g_offsets[n + 1] + g_blockoff[(n + 1) >> 8];

    float4 acc  = make_float4(0.f, 0.f, 0.f, 0.f);
    float  ssum = 0.f;          // running sum of exp(logit) (uniform across lanes)

    if (end > start) {
        // per-lane weights + this node's dst feature row (read once)
        const float4 wp  = ((const float4*)W_pi)[lane];
        const float4 wm1 = ((const float4*)W_M)[lane];          // prod part
        const float4 wm2 = ((const float4*)(W_M + DIM))[lane];  // h_d part
        const float4 fdv = ((const float4*)(h_v + (size_t)n * DIM))[lane];

        for (int i = start; i < end; i += 4) {
            const int last = end - 1;
            const int iB = min(i + 1, last);
            const int iC = min(i + 2, last);
            const int iD = min(i + 3, last);
            const bool hasB = (i + 1 < end);
            const bool hasC = (i + 2 < end);
            const bool hasD = (i + 3 < end);

            // ---- issue all 8 row-gathers up front ----
            const int2 sa = __ldg(&g_csr[i]);
            const int2 sb = __ldg(&g_csr[iB]);
            const int2 sc = __ldg(&g_csr[iC]);
            const int2 sd = __ldg(&g_csr[iD]);

            const float4 fa = ((const float4*)(h_v + (size_t)sa.x * DIM))[lane];
            const float4 fb = ((const float4*)(h_v + (size_t)sb.x * DIM))[lane];
            const float4 fc = ((const float4*)(h_v + (size_t)sc.x * DIM))[lane];
            const float4 fe = ((const float4*)(h_v + (size_t)sd.x * DIM))[lane];
            const float4 ha = __ldcs((const float4*)(h_d + (size_t)sa.y * DIM) + lane);
            const float4 hb = __ldcs((const float4*)(h_d + (size_t)sb.y * DIM) + lane);
            const float4 hc = __ldcs((const float4*)(h_d + (size_t)sc.y * DIM) + lane);
            const float4 he = __ldcs((const float4*)(h_d + (size_t)sd.y * DIM) + lane);

            // ---- per-edge partial dots over this lane's 4 dims ----
            const float pa0 = fa.x * fdv.x, pa1 = fa.y * fdv.y;
            const float pa2 = fa.z * fdv.z, pa3 = fa.w * fdv.w;
            float d1a = pa0 * ha.x * wp.x + pa1 * ha.y * wp.y
                      + pa2 * ha.z * wp.z + pa3 * ha.w * wp.w;
            float d2a = pa0 * wm1.x + pa1 * wm1.y + pa2 * wm1.z + pa3 * wm1.w
                      + ha.x * wm2.x + ha.y * wm2.y + ha.z * wm2.z + ha.w * wm2.w;

            const float pb0 = fb.x * fdv.x, pb1 = fb.y * fdv.y;
            const float pb2 = fb.z * fdv.z, pb3 = fb.w * fdv.w;
            float d1b = pb0 * hb.x * wp.x + pb1 * hb.y * wp.y
                      + pb2 * hb.z * wp.z + pb3 * hb.w * wp.w;
            float d2b = pb0 * wm1.x + pb1 * wm1.y + pb2 * wm1.z + pb3 * wm1.w
                      + hb.x * wm2.x + hb.y * wm2.y + hb.z * wm2.z + hb.w * wm2.w;

            const float pc0 = fc.x * fdv.x, pc1 = fc.y * fdv.y;
            const float pc2 = fc.z * fdv.z, pc3 = fc.w * fdv.w;
            float d1c = pc0 * hc.x * wp.x + pc1 * hc.y * wp.y
                      + pc2 * hc.z * wp.z + pc3 * hc.w * wp.w;
            float d2c = pc0 * wm1.x + pc1 * wm1.y + pc2 * wm1.z + pc3 * wm1.w
                      + hc.x * wm2.x + hc.y * wm2.y + hc.z * wm2.z + hc.w * wm2.w;

            const float pe0 = fe.x * fdv.x, pe1 = fe.y * fdv.y;
            const float pe2 = fe.z * fdv.z, pe3 = fe.w * fdv.w;
            float d1e = pe0 * he.x * wp.x + pe1 * he.y * wp.y
                      + pe2 * he.z * wp.z + pe3 * he.w * wp.w;
            float d2e = pe0 * wm1.x + pe1 * wm1.y + pe2 * wm1.z + pe3 * wm1.w
                      + he.x * wm2.x + he.y * wm2.y + he.z * wm2.z + he.w * wm2.w;

            // ---- 8 interleaved 5-level reductions ----
            #pragma unroll
            for (int off = 16; off > 0; off >>= 1) {
                d1a += __shfl_xor_sync(0xFFFFFFFFu, d1a, off);
                d2a += __shfl_xor_sync(0xFFFFFFFFu, d2a, off);
                d1b += __shfl_xor_sync(0xFFFFFFFFu, d1b, off);
                d2b += __shfl_xor_sync(0xFFFFFFFFu, d2b, off);
                d1c += __shfl_xor_sync(0xFFFFFFFFu, d1c, off);
                d2c += __shfl_xor_sync(0xFFFFFFFFu, d2c, off);
                d1e += __shfl_xor_sync(0xFFFFFFFFu, d1e, off);
                d2e += __shfl_xor_sync(0xFFFFFFFFu, d2e, off);
            }

            const float pA = __expf(d1a * __fdividef(1.0f, 1.0f + __expf(-d2a)));
            float pB = __expf(d1b * __fdividef(1.0f, 1.0f + __expf(-d2b)));
            float pC = __expf(d1c * __fdividef(1.0f, 1.0f + __expf(-d2c)));
            float pD = __expf(d1e * __fdividef(1.0f, 1.0f + __expf(-d2e)));
            pB = hasB ? pB : 0.0f;
            pC = hasC ? pC : 0.0f;
            pD = hasD ? pD : 0.0f;

            ssum  += (pA + pB) + (pC + pD);
            acc.x += pA * fa.x + pB * fb.x + pC * fc.x + pD * fe.x;
            acc.y += pA * fa.y + pB * fb.y + pC * fc.y + pD * fe.y;
            acc.z += pA * fa.z + pB * fb.z + pC * fc.z + pD * fe.z;
            acc.w += pA * fa.w + pB * fb.w + pC * fc.w + pD * fe.w;
        }
        const float inv = 1.0f / ssum;
        acc.x *= inv; acc.y *= inv; acc.z *= inv; acc.w *= inv;
    }
    ((float4*)(out + (size_t)n * DIM))[lane] = acc;   // single coalesced store
}

// ---------------- launch --------------------------------------------------------
extern "C" void kernel_launch(void* const* d_in, const int* in_sizes, int n_in,
                              void* d_out, int out_size) {
    const float* h_v  = (const float*)d_in[0];
    const float* h_d  = (const float*)d_in[1];
    const float* W_pi = (const float*)d_in[2];
    const float* W_M  = (const float*)d_in[3];
    const int*   src  = (const int*)d_in[4];
    const int*   dst  = (const int*)d_in[5];
    float*       out  = (float*)d_out;

    void* count_addr = nullptr;
    cudaGetSymbolAddress(&count_addr, g_count);
    cudaMemsetAsync(count_addr, 0, N_NODES * sizeof(int));

    count_kernel<<<(N_EDGES + 255) / 256, 256>>>(dst);
    scanA_kernel<<<SCAN_NBLKS, SCAN_BLK>>>();
    scanB_kernel<<<1, SCAN_BLK>>>();
    scatter_kernel<<<(N_EDGES + 255) / 256, 256>>>(src, dst);

    fused_node_kernel<<<(N_NODES * 32 + 127) / 128, 128>>>(h_v, h_d, W_pi, W_M, out);
}